// round 16
// baseline (speedup 1.0000x reference)
#include <cuda_runtime.h>
#include <cuda_fp16.h>
#include <math.h>
#include <stdint.h>

#define BB 8
#define LL 512
#define DM 1024
#define NH 16
#define HD 64
#define BH (BB*NH)     // 128

// ---- scratch (device globals; allocation-free rule) ----
__device__ float  g_q  [(size_t)BH*LL*HD];
__device__ float  g_v  [(size_t)BH*LL*HD];
__device__ float  g_rot[(size_t)LL*64];
__device__ __align__(16) __half g_xh [(size_t)4096*1024];
__device__ __align__(16) __half g_xl [(size_t)4096*1024];
__device__ __align__(16) __half g_wth[(size_t)2048*1024];
__device__ __align__(16) __half g_wtl[(size_t)2048*1024];
__device__ __align__(16) __half g_qeh[(size_t)BH*LL*128];
__device__ __align__(16) __half g_qel[(size_t)BH*LL*128];
__device__ __align__(16) __half g_keh[(size_t)BH*LL*128];
__device__ __align__(16) __half g_kel[(size_t)BH*LL*128];
__device__ __align__(16) __half g_vth[(size_t)BH*HD*LL];
__device__ __align__(16) __half g_vtl[(size_t)BH*HD*LL];

// ---------------------------------------------------------------------------
__device__ __forceinline__ uint32_t pack2h(__half a, __half b) {
    __half2 p = __halves2half2(a, b);
    return *reinterpret_cast<uint32_t*>(&p);
}
__device__ __forceinline__ void split4(float4 v, uint2& hi, uint2& lo) {
    __half h0 = __float2half_rn(v.x), h1 = __float2half_rn(v.y);
    __half h2 = __float2half_rn(v.z), h3 = __float2half_rn(v.w);
    hi.x = pack2h(h0, h1); hi.y = pack2h(h2, h3);
    lo.x = pack2h(__float2half_rn(v.x - __half2float(h0)),
                  __float2half_rn(v.y - __half2float(h1)));
    lo.y = pack2h(__float2half_rn(v.z - __half2float(h2)),
                  __float2half_rn(v.w - __half2float(h3)));
}
// f32-accumulator HMMA (main term)
__device__ __forceinline__ void mma_f16(float* c, const uint32_t* a, const uint32_t* b) {
    asm volatile(
        "mma.sync.aligned.m16n8k16.row.col.f32.f16.f16.f32 "
        "{%0,%1,%2,%3}, {%4,%5,%6,%7}, {%8,%9}, {%0,%1,%2,%3};\n"
        : "+f"(c[0]), "+f"(c[1]), "+f"(c[2]), "+f"(c[3])
        : "r"(a[0]), "r"(a[1]), "r"(a[2]), "r"(a[3]), "r"(b[0]), "r"(b[1]));
}
// f16-accumulator HMMA (correction terms; 2 C-regs, f16x2 each)
__device__ __forceinline__ void mma_f16a(uint32_t* c, const uint32_t* a, const uint32_t* b) {
    asm volatile(
        "mma.sync.aligned.m16n8k16.row.col.f16.f16.f16.f16 "
        "{%0,%1}, {%2,%3,%4,%5}, {%6,%7}, {%0,%1};\n"
        : "+r"(c[0]), "+r"(c[1])
        : "r"(a[0]), "r"(a[1]), "r"(a[2]), "r"(a[3]), "r"(b[0]), "r"(b[1]));
}
__device__ __forceinline__ float2 h2f2(uint32_t u) {
    __half2 h = *reinterpret_cast<__half2*>(&u);
    return __half22float2(h);
}
__device__ __forceinline__ void ldsm4(uint32_t* r, uint32_t addr) {
    asm volatile("ldmatrix.sync.aligned.m8n8.x4.shared.b16 {%0,%1,%2,%3}, [%4];"
                 : "=r"(r[0]), "=r"(r[1]), "=r"(r[2]), "=r"(r[3]) : "r"(addr));
}
__device__ __forceinline__ uint32_t smem_u32(const void* p) {
    return (uint32_t)__cvta_generic_to_shared(p);
}
__device__ __forceinline__ void cp16(void* dst, const void* src) {
    uint32_t s = (uint32_t)__cvta_generic_to_shared(dst);
    asm volatile("cp.async.cg.shared.global [%0], [%1], 16;\n" :: "r"(s), "l"(src));
}
#define CP_COMMIT asm volatile("cp.async.commit_group;\n")
#define CP_WAIT1  asm volatile("cp.async.wait_group 1;\n")
#define CP_WAIT0  asm volatile("cp.async.wait_group 0;\n")

// ---------------------------------------------------------------------------
__global__ void rot_kernel() {
    int k = blockIdx.x, d = threadIdx.x;
    int i = d & 31;
    float w = expf(-(float)i * (logf(10000.0f) / 31.0f));
    float ang = (float)k * w;
    g_rot[k * 64 + d] = (d < 32) ? sinf(ang) : cosf(ang);
}

__global__ __launch_bounds__(256) void prep_x(const float* __restrict__ X) {
    int idx = blockIdx.x * 256 + threadIdx.x;
    float4 v = ((const float4*)X)[idx];
    uint2 hi, lo; split4(v, hi, lo);
    ((uint2*)g_xh)[idx] = hi;
    ((uint2*)g_xl)[idx] = lo;
}

__global__ __launch_bounds__(256) void prep_w(const float* __restrict__ W) {
    __shared__ float tile[32][33];
    int n0 = blockIdx.x * 32, k0 = blockIdx.y * 32;
    int t = threadIdx.x;
    int row = t >> 3, c4 = (t & 7) * 4;
    float4 v = *(const float4*)&W[(size_t)(k0 + row) * 2048 + n0 + c4];
    tile[row][c4 + 0] = v.x; tile[row][c4 + 1] = v.y;
    tile[row][c4 + 2] = v.z; tile[row][c4 + 3] = v.w;
    __syncthreads();
    float4 o = make_float4(tile[c4 + 0][row], tile[c4 + 1][row],
                           tile[c4 + 2][row], tile[c4 + 3][row]);
    uint2 hi, lo; split4(o, hi, lo);
    *(uint2*)&g_wth[(size_t)(n0 + row) * 1024 + k0 + c4] = hi;
    *(uint2*)&g_wtl[(size_t)(n0 + row) * 1024 + k0 + c4] = lo;
}

// ---------------------------------------------------------------------------
// qv GEMM: 128x64 CTA tile, 3-term split; main term f32-accum, correction
// terms f16-accum (2x rate hypothesis). ldmatrix + 2-stage cp.async. BK=32.
// ---------------------------------------------------------------------------
#define QV_PA (128*40)
#define QV_PB (64*40)
#define QV_SS (2*QV_PA + 2*QV_PB)
#define QV_SMEM (2*QV_SS*2)

__device__ __forceinline__ void qv_issue(__half* qsm, int stage, int k0,
                                         int m0, int n0, int t) {
    __half* base = qsm + stage * QV_SS;
    #pragma unroll
    for (int i = 0; i < 2; i++) {
        int c = t + 256 * i;
        int row = c >> 2, seg = (c & 3) * 8;
        size_t ga = (size_t)(m0 + row) * 1024 + k0 + seg;
        cp16(base + row * 40 + seg,          g_xh + ga);
        cp16(base + QV_PA + row * 40 + seg,  g_xl + ga);
    }
    {
        int row = t >> 2, seg = (t & 3) * 8;
        size_t gb = (size_t)(n0 + row) * 1024 + k0 + seg;
        cp16(base + 2 * QV_PA + row * 40 + seg,          g_wth + gb);
        cp16(base + 2 * QV_PA + QV_PB + row * 40 + seg,  g_wtl + gb);
    }
}

__global__ __launch_bounds__(256, 2) void qv_gemm_f16() {
    extern __shared__ __half qsm[];
    int t = threadIdx.x, lane = t & 31, warp = t >> 5;
    int m0 = blockIdx.y * 128, n0 = blockIdx.x * 64;
    int wm = (warp >> 1) * 32, wn = (warp & 1) * 32;
    int r = lane >> 2, c2 = (lane & 3) * 2;

    int lane7 = lane & 7;
    int lrow = lane7 + ((lane >> 3) & 1) * 8;
    int acol = ((lane >> 4) & 1) * 8;
    uint32_t offA0 = ((wm + lrow) * 40 + acol) * 2;
    uint32_t offA1 = ((wm + 16 + lrow) * 40 + acol) * 2;
    int brow = ((lane >> 4) & 1) * 8 + lane7;
    int bcol = ((lane >> 3) & 1) * 8;
    uint32_t offB[2];
    #pragma unroll
    for (int j = 0; j < 2; j++) offB[j] = ((wn + j * 16 + brow) * 40 + bcol) * 2;
    uint32_t sQ = smem_u32(qsm);

    float acc[2][4][4];
    uint32_t accc[2][4][2];
    #pragma unroll
    for (int mt = 0; mt < 2; mt++)
        #pragma unroll
        for (int nt = 0; nt < 4; nt++) {
            #pragma unroll
            for (int j = 0; j < 4; j++) acc[mt][nt][j] = 0.f;
            accc[mt][nt][0] = 0u; accc[mt][nt][1] = 0u;
        }

    qv_issue(qsm, 0, 0, m0, n0, t);
    CP_COMMIT;

    for (int it = 0; it < 32; it++) {
        if (it < 31) {
            qv_issue(qsm, (it + 1) & 1, (it + 1) * 32, m0, n0, t);
            CP_COMMIT;
            CP_WAIT1;
        } else {
            CP_WAIT0;
        }
        __syncthreads();

        uint32_t stB = sQ + (it & 1) * (QV_SS * 2);
        uint32_t aH = stB;
        uint32_t aL = stB + QV_PA * 2;
        uint32_t bH = stB + 2 * QV_PA * 2;
        uint32_t bL = stB + (2 * QV_PA + QV_PB) * 2;

        #pragma unroll
        for (int s = 0; s < 2; s++) {
            uint32_t ah0[4], ah1[4], al0[4], al1[4];
            ldsm4(ah0, aH + offA0 + s * 32);
            ldsm4(ah1, aH + offA1 + s * 32);
            ldsm4(al0, aL + offA0 + s * 32);
            ldsm4(al1, aL + offA1 + s * 32);
            #pragma unroll
            for (int j = 0; j < 2; j++) {
                uint32_t b_h[4], b_l[4];
                ldsm4(b_h, bH + offB[j] + s * 32);
                ldsm4(b_l, bL + offB[j] + s * 32);
                // main: Ah x Bh (f32 accum)
                mma_f16(acc[0][2 * j],     ah0, &b_h[0]);
                mma_f16(acc[1][2 * j],     ah1, &b_h[0]);
                mma_f16(acc[0][2 * j + 1], ah0, &b_h[2]);
                mma_f16(acc[1][2 * j + 1], ah1, &b_h[2]);
                // corrections: Ah x Bl + Al x Bh (f16 accum)
                mma_f16a(accc[0][2 * j],     ah0, &b_l[0]);
                mma_f16a(accc[1][2 * j],     ah1, &b_l[0]);
                mma_f16a(accc[0][2 * j + 1], ah0, &b_l[2]);
                mma_f16a(accc[1][2 * j + 1], ah1, &b_l[2]);
                mma_f16a(accc[0][2 * j],     al0, &b_h[0]);
                mma_f16a(accc[1][2 * j],     al1, &b_h[0]);
                mma_f16a(accc[0][2 * j + 1], al0, &b_h[2]);
                mma_f16a(accc[1][2 * j + 1], al1, &b_h[2]);
            }
        }
        __syncthreads();
    }

    #pragma unroll
    for (int mt = 0; mt < 2; mt++) {
        #pragma unroll
        for (int nt = 0; nt < 4; nt++) {
            int r0 = m0 + wm + mt * 16 + r;
            int cc = n0 + wn + nt * 8 + c2;
            #pragma unroll
            for (int half_ = 0; half_ < 2; half_++) {
                int m = r0 + half_ * 8;
                float2 cadd = h2f2(accc[mt][nt][half_]);
                float2 val = make_float2(acc[mt][nt][half_ * 2] + cadd.x,
                                         acc[mt][nt][half_ * 2 + 1] + cadd.y);
                int bi = m >> 9, l = m & 511;
                if (cc < 1024) {
                    int h = cc >> 6, d = cc & 63;
                    *(float2*)&g_q[(((size_t)(bi * 16 + h) * 512) + l) * 64 + d] = val;
                } else {
                    int n2 = cc - 1024;
                    int h = n2 >> 6, d = n2 & 63;
                    *(float2*)&g_v[(((size_t)(bi * 16 + h) * 512) + l) * 64 + d] = val;
                }
            }
        }
    }
}

// ---------------------------------------------------------------------------
__global__ __launch_bounds__(256) void qe_build(const float* __restrict__ rr,
                                                const float* __restrict__ rw) {
    __shared__ float u[4][64];
    int bh = blockIdx.x, h = bh & 15;
    int row = threadIdx.x >> 6;
    int d = threadIdx.x & 63;
    int q = blockIdx.y * 4 + row;

    float qv = g_q[((size_t)bh * 512 + q) * 64 + d];
    float outA = qv + rr[h * 64 + d];
    float uu = qv + rw[h * 64 + d];
    u[row][d] = uu;
    __syncthreads();
    int i = d & 31;
    float sq = g_rot[q * 64 + i];
    float cq = g_rot[q * 64 + 32 + i];
    float partner = u[row][d ^ 32];
    float outB = uu * cq + ((d < 32) ? partner : -partner) * sq;

    size_t base = ((size_t)bh * 512 + q) * 128;
    __half ha = __float2half_rn(outA);
    __half hb = __float2half_rn(outB);
    g_qeh[base + d] = ha;
    g_qeh[base + 64 + d] = hb;
    g_qel[base + d] = __float2half_rn(outA - __half2float(ha));
    g_qel[base + 64 + d] = __float2half_rn(outB - __half2float(hb));
}

__global__ __launch_bounds__(256) void ke_build(const float* __restrict__ X) {
    int bh = blockIdx.x;
    int b = bh >> 4, h = bh & 15;
    int kbase = blockIdx.y * 64;
    for (int i = threadIdx.x; i < 64 * 128; i += 256) {
        int k = kbase + (i >> 7), c = i & 127;
        float f = (c < 64) ? X[((size_t)(b * 512) + k) * 1024 + h * 64 + c]
                           : g_rot[k * 64 + (c - 64)];
        __half hi = __float2half_rn(f);
        size_t o = ((size_t)bh * 512 + k) * 128 + c;
        g_keh[o] = hi;
        g_kel[o] = __float2half_rn(f - __half2float(hi));
    }
}

__global__ __launch_bounds__(256) void build_vt() {
    __shared__ float tile[64][65];
    int bh = blockIdx.x;
    int k0 = blockIdx.y * 64;
    int t = threadIdx.x;
    #pragma unroll
    for (int i = 0; i < 4; i++) {
        int idx = t + 256 * i;
        int kk = idx >> 4, d4 = (idx & 15) * 4;
        float4 v = *(const float4*)&g_v[((size_t)bh * 512 + k0 + kk) * 64 + d4];
        tile[kk][d4 + 0] = v.x; tile[kk][d4 + 1] = v.y;
        tile[kk][d4 + 2] = v.z; tile[kk][d4 + 3] = v.w;
    }
    __syncthreads();
    #pragma unroll
    for (int i = 0; i < 4; i++) {
        int idx = t + 256 * i;
        int d = idx >> 4, kk4 = (idx & 15) * 4;
        float4 o = make_float4(tile[kk4 + 0][d], tile[kk4 + 1][d],
                               tile[kk4 + 2][d], tile[kk4 + 3][d]);
        uint2 hi, lo; split4(o, hi, lo);
        *(uint2*)&g_vth[((size_t)bh * 64 + d) * 512 + k0 + kk4] = hi;
        *(uint2*)&g_vtl[((size_t)bh * 64 + d) * 512 + k0 + kk4] = lo;
    }
}

// ---------------------------------------------------------------------------
// Flash attention: q-tile 128, 256 threads, 2-stage cp.async, ldmatrix,
// Q hoisted. Main S/PV terms f32-accum; correction terms f16-accum.
// ---------------------------------------------------------------------------
#define QK_STR 136
#define V_STR  72
#define F_QSZ (128*QK_STR)
#define F_KSZ (64*QK_STR)
#define F_VSZ (64*V_STR)
#define F_KBASE (2*F_QSZ)
#define F_VBASE (2*F_QSZ + 4*F_KSZ)
#define F_END   (2*F_QSZ + 4*F_KSZ + 4*F_VSZ)
#define FLASH_SMEM (F_END*2 + 512*4)

__device__ __forceinline__ void flash_issue_kv(__half* sh, int stage, int k0,
                                               int bh, int t) {
    __half* Kh = sh + F_KBASE + stage * 2 * F_KSZ;
    __half* Kl = Kh + F_KSZ;
    __half* Vh = sh + F_VBASE + stage * 2 * F_VSZ;
    __half* Vl = Vh + F_VSZ;
    #pragma unroll
    for (int i = 0; i < 4; i++) {
        int c = t + 256 * i;
        int k = c >> 4, seg = (c & 15) * 8;
        size_t g = ((size_t)bh * 512 + k0 + k) * 128 + seg;
        cp16(Kh + k * QK_STR + seg, g_keh + g);
        cp16(Kl + k * QK_STR + seg, g_kel + g);
    }
    #pragma unroll
    for (int i = 0; i < 2; i++) {
        int c = t + 256 * i;
        int d = c >> 3, seg = (c & 7) * 8;
        size_t g = ((size_t)bh * 64 + d) * 512 + k0 + seg;
        cp16(Vh + d * V_STR + seg, g_vth + g);
        cp16(Vl + d * V_STR + seg, g_vtl + g);
    }
}

__global__ __launch_bounds__(256) void flash_attn(const float* __restrict__ mask,
                                                  float* __restrict__ out) {
    extern __shared__ __half sh[];
    float* ms = (float*)(sh + F_END);

    int qt = blockIdx.x, bh = blockIdx.y;
    int b = bh >> 4, h = bh & 15;
    int q0 = qt * 128;
    int t = threadIdx.x, lane = t & 31, warp = t >> 5;
    int r = lane >> 2, c2 = (lane & 3) * 2;
    int wq = warp * 16;

    int lane7 = lane & 7;
    int lrow = lane7 + ((lane >> 3) & 1) * 8;
    int acol = ((lane >> 4) & 1) * 8;
    uint32_t offQ = ((wq + lrow) * QK_STR + acol) * 2;
    int brow = ((lane >> 4) & 1) * 8 + lane7;
    int bcol = ((lane >> 3) & 1) * 8;
    uint32_t offK[4], offV[4];
    #pragma unroll
    for (int j = 0; j < 4; j++) {
        offK[j] = ((j * 16 + brow) * QK_STR + bcol) * 2;
        offV[j] = ((j * 16 + brow) * V_STR + bcol) * 2;
    }
    uint32_t sF = smem_u32(sh);

    #pragma unroll
    for (int i = 0; i < 8; i++) {
        int c = t + 256 * i;
        int q = c >> 4, seg = (c & 15) * 8;
        size_t g = ((size_t)bh * 512 + q0 + q) * 128 + seg;
        cp16(sh + q * QK_STR + seg, g_qeh + g);
        cp16(sh + F_QSZ + q * QK_STR + seg, g_qel + g);
    }
    flash_issue_kv(sh, 0, 0, bh, t);
    CP_COMMIT;

    ms[t] = mask[b * 512 + t];
    ms[t + 256] = mask[b * 512 + t + 256];

    float m_run[2] = {-1e30f, -1e30f}, l_run[2] = {0.f, 0.f};
    float o[8][4];
    #pragma unroll
    for (int nt = 0; nt < 8; nt++)
        #pragma unroll
        for (int j = 0; j < 4; j++) o[nt][j] = 0.f;

    uint32_t qh[8][4], ql[8][4];

    for (int it = 0; it < 8; it++) {
        if (it < 7) {
            flash_issue_kv(sh, (it + 1) & 1, (it + 1) * 64, bh, t);
            CP_COMMIT;
            CP_WAIT1;
        } else {
            CP_WAIT0;
        }
        __syncthreads();

        if (it == 0) {
            #pragma unroll
            for (int st = 0; st < 8; st++) {
                ldsm4(qh[st], sF + offQ + st * 32);
                ldsm4(ql[st], sF + F_QSZ * 2 + offQ + st * 32);
            }
        }

        uint32_t aKh = sF + (F_KBASE + (it & 1) * 2 * F_KSZ) * 2;
        uint32_t aKl = aKh + F_KSZ * 2;
        uint32_t aVh = sF + (F_VBASE + (it & 1) * 2 * F_VSZ) * 2;
        uint32_t aVl = aVh + F_VSZ * 2;
        int k0 = it * 64;

        // ---- S = Qe . Ke^T : main f32, corrections f16 ----
        float s[8][4];
        uint32_t sc[8][2];
        #pragma unroll
        for (int nt = 0; nt < 8; nt++) {
            #pragma unroll
            for (int j = 0; j < 4; j++) s[nt][j] = 0.f;
            sc[nt][0] = 0u; sc[nt][1] = 0u;
        }

        #pragma unroll
        for (int st = 0; st < 8; st++) {
            #pragma unroll
            for (int j = 0; j < 4; j++) {
                uint32_t kh4[4], kl4[4];
                ldsm4(kh4, aKh + offK[j] + st * 32);
                ldsm4(kl4, aKl + offK[j] + st * 32);
                mma_f16(s[2 * j],     qh[st], &kh4[0]);
                mma_f16(s[2 * j + 1], qh[st], &kh4[2]);
                mma_f16a(sc[2 * j],     qh[st], &kl4[0]);
                mma_f16a(sc[2 * j + 1], qh[st], &kl4[2]);
                mma_f16a(sc[2 * j],     ql[st], &kh4[0]);
                mma_f16a(sc[2 * j + 1], ql[st], &kh4[2]);
            }
        }
        #pragma unroll
        for (int nt = 0; nt < 8; nt++) {
            float2 a0 = h2f2(sc[nt][0]);
            float2 a1 = h2f2(sc[nt][1]);
            s[nt][0] += a0.x; s[nt][1] += a0.y;
            s[nt][2] += a1.x; s[nt][3] += a1.y;
        }

        // ---- mask + online softmax ----
        float mnew0 = m_run[0], mnew1 = m_run[1];
        #pragma unroll
        for (int nt = 0; nt < 8; nt++) {
            int kc = k0 + nt * 8 + c2;
            float mk0 = ms[kc], mk1 = ms[kc + 1];
            float v0 = s[nt][0] * mk0; s[nt][0] = (v0 == 0.f) ? -INFINITY : v0;
            float v1 = s[nt][1] * mk1; s[nt][1] = (v1 == 0.f) ? -INFINITY : v1;
            float v2 = s[nt][2] * mk0; s[nt][2] = (v2 == 0.f) ? -INFINITY : v2;
            float v3 = s[nt][3] * mk1; s[nt][3] = (v3 == 0.f) ? -INFINITY : v3;
            mnew0 = fmaxf(mnew0, fmaxf(s[nt][0], s[nt][1]));
            mnew1 = fmaxf(mnew1, fmaxf(s[nt][2], s[nt][3]));
        }
        #pragma unroll
        for (int off = 1; off <= 2; off <<= 1) {
            mnew0 = fmaxf(mnew0, __shfl_xor_sync(0xffffffffu, mnew0, off));
            mnew1 = fmaxf(mnew1, __shfl_xor_sync(0xffffffffu, mnew1, off));
        }
        float corr0 = __expf(m_run[0] - mnew0);
        float corr1 = __expf(m_run[1] - mnew1);
        float ts0 = 0.f, ts1 = 0.f;
        #pragma unroll
        for (int nt = 0; nt < 8; nt++) {
            float p0 = __expf(s[nt][0] - mnew0); s[nt][0] = p0;
            float p1 = __expf(s[nt][1] - mnew0); s[nt][1] = p1;
            float p2 = __expf(s[nt][2] - mnew1); s[nt][2] = p2;
            float p3 = __expf(s[nt][3] - mnew1); s[nt][3] = p3;
            ts0 += p0 + p1; ts1 += p2 + p3;
        }
        #pragma unroll
        for (int off = 1; off <= 2; off <<= 1) {
            ts0 += __shfl_xor_sync(0xffffffffu, ts0, off);
            ts1 += __shfl_xor_sync(0xffffffffu, ts1, off);
        }
        l_run[0] = l_run[0] * corr0 + ts0;
        l_run[1] = l_run[1] * corr1 + ts1;
        m_run[0] = mnew0; m_run[1] = mnew1;
        #pragma unroll
        for (int nt = 0; nt < 8; nt++) {
            o[nt][0] *= corr0; o[nt][1] *= corr0;
            o[nt][2] *= corr1; o[nt][3] *= corr1;
        }

        // ---- O += P . V : main f32, corrections f16 (fresh per iter) ----
        uint32_t oc[8][2];
        #pragma unroll
        for (int nt = 0; nt < 8; nt++) { oc[nt][0] = 0u; oc[nt][1] = 0u; }

        #pragma unroll
        for (int s2 = 0; s2 < 4; s2++) {
            float* pa = s[2 * s2];
            float* pb = s[2 * s2 + 1];
            __half h00 = __float2half_rn(pa[0]), h01 = __float2half_rn(pa[1]);
            __half h02 = __float2half_rn(pa[2]), h03 = __float2half_rn(pa[3]);
            __half h10 = __float2half_rn(pb[0]), h11 = __float2half_rn(pb[1]);
            __half h12 = __float2half_rn(pb[2]), h13 = __float2half_rn(pb[3]);
            uint32_t ph[4], pl[4];
            ph[0] = pack2h(h00, h01);
            ph[1] = pack2h(h02, h03);
            ph[2] = pack2h(h10, h11);
            ph[3] = pack2h(h12, h13);
            pl[0] = pack2h(__float2half_rn(pa[0] - __half2float(h00)),
                           __float2half_rn(pa[1] - __half2float(h01)));
            pl[1] = pack2h(__float2half_rn(pa[2] - __half2float(h02)),
                           __float2half_rn(pa[3] - __half2float(h03)));
            pl[2] = pack2h(__float2half_rn(pb[0] - __half2float(h10)),
                           __float2half_rn(pb[1] - __half2float(h11)));
            pl[3] = pack2h(__float2half_rn(pb[2] - __half2float(h12)),
                           __float2half_rn(pb[3] - __half2float(h13)));
            #pragma unroll
            for (int j = 0; j < 4; j++) {
                uint32_t vh4[4], vl4[4];
                ldsm4(vh4, aVh + offV[j] + s2 * 32);
                ldsm4(vl4, aVl + offV[j] + s2 * 32);
                mma_f16(o[2 * j],     ph, &vh4[0]);
                mma_f16(o[2 * j + 1], ph, &vh4[2]);
                mma_f16a(oc[2 * j],     ph, &vl4[0]);
                mma_f16a(oc[2 * j + 1], ph, &vl4[2]);
                mma_f16a(oc[2 * j],     pl, &vh4[0]);
                mma_f16a(oc[2 * j + 1], pl, &vh4[2]);
            }
        }
        #pragma unroll
        for (int nt = 0; nt < 8; nt++) {
            float2 a0 = h2f2(oc[nt][0]);
            float2 a1 = h2f2(oc[nt][1]);
            o[nt][0] += a0.x; o[nt][1] += a0.y;
            o[nt][2] += a1.x; o[nt][3] += a1.y;
        }
        __syncthreads();
    }

    float inv0 = 1.0f / l_run[0], inv1 = 1.0f / l_run[1];
    int qg0 = q0 + wq + r;
    #pragma unroll
    for (int ntd = 0; ntd < 8; ntd++) {
        int d = ntd * 8 + c2;
        *(float2*)&out[((size_t)(b * 512) + qg0) * 1024 + h * 64 + d] =
            make_float2(o[ntd][0] * inv0, o[ntd][1] * inv0);
        *(float2*)&out[((size_t)(b * 512) + qg0 + 8) * 1024 + h * 64 + d] =
            make_float2(o[ntd][2] * inv1, o[ntd][3] * inv1);
    }
}

// ---------------------------------------------------------------------------
extern "C" void kernel_launch(void* const* d_in, const int* in_sizes, int n_in,
                              void* d_out, int out_size) {
    const float* x    = (const float*)d_in[0];
    const float* mask = (const float*)d_in[1];
    const float* W    = (const float*)d_in[2];
    const float* rr   = (const float*)d_in[3];
    const float* rw   = (const float*)d_in[4];
    float* out = (float*)d_out;

    cudaFuncSetAttribute(qv_gemm_f16, cudaFuncAttributeMaxDynamicSharedMemorySize,
                         QV_SMEM);
    cudaFuncSetAttribute(flash_attn, cudaFuncAttributeMaxDynamicSharedMemorySize,
                         FLASH_SMEM);

    rot_kernel<<<512, 64>>>();
    prep_x<<<4096, 256>>>(x);
    prep_w<<<dim3(64, 32), 256>>>(W);
    qv_gemm_f16<<<dim3(32, 32), 256, QV_SMEM>>>();
    qe_build<<<dim3(128, 128), 256>>>(rr, rw);
    ke_build<<<dim3(128, 8), 256>>>(x);
    build_vt<<<dim3(128, 8), 256>>>();
    flash_attn<<<dim3(4, 128), 256, FLASH_SMEM>>>(mask, out);
}

// round 17
// speedup vs baseline: 1.0831x; 1.0831x over previous
#include <cuda_runtime.h>
#include <cuda_fp16.h>
#include <math.h>
#include <stdint.h>

#define BB 8
#define LL 512
#define DM 1024
#define NH 16
#define HD 64
#define BH (BB*NH)     // 128

// ---- scratch (device globals; allocation-free rule) ----
__device__ float  g_q  [(size_t)BH*LL*HD];
__device__ float  g_v  [(size_t)BH*LL*HD];
__device__ float  g_rot[(size_t)LL*64];
__device__ __align__(16) __half g_xh [(size_t)4096*1024];
__device__ __align__(16) __half g_xl [(size_t)4096*1024];
__device__ __align__(16) __half g_wth[(size_t)2048*1024];
__device__ __align__(16) __half g_wtl[(size_t)2048*1024];
__device__ __align__(16) __half g_qeh[(size_t)BH*LL*128];
__device__ __align__(16) __half g_qel[(size_t)BH*LL*128];
__device__ __align__(16) __half g_keh[(size_t)BH*LL*128];
__device__ __align__(16) __half g_kel[(size_t)BH*LL*128];
__device__ __align__(16) __half g_vth[(size_t)BH*HD*LL];
__device__ __align__(16) __half g_vtl[(size_t)BH*HD*LL];

// ---------------------------------------------------------------------------
__device__ __forceinline__ uint32_t pack2h(__half a, __half b) {
    __half2 p = __halves2half2(a, b);
    return *reinterpret_cast<uint32_t*>(&p);
}
__device__ __forceinline__ void split4(float4 v, uint2& hi, uint2& lo) {
    __half h0 = __float2half_rn(v.x), h1 = __float2half_rn(v.y);
    __half h2 = __float2half_rn(v.z), h3 = __float2half_rn(v.w);
    hi.x = pack2h(h0, h1); hi.y = pack2h(h2, h3);
    lo.x = pack2h(__float2half_rn(v.x - __half2float(h0)),
                  __float2half_rn(v.y - __half2float(h1)));
    lo.y = pack2h(__float2half_rn(v.z - __half2float(h2)),
                  __float2half_rn(v.w - __half2float(h3)));
}
__device__ __forceinline__ void mma_f16(float* c, const uint32_t* a, const uint32_t* b) {
    asm volatile(
        "mma.sync.aligned.m16n8k16.row.col.f32.f16.f16.f32 "
        "{%0,%1,%2,%3}, {%4,%5,%6,%7}, {%8,%9}, {%0,%1,%2,%3};\n"
        : "+f"(c[0]), "+f"(c[1]), "+f"(c[2]), "+f"(c[3])
        : "r"(a[0]), "r"(a[1]), "r"(a[2]), "r"(a[3]), "r"(b[0]), "r"(b[1]));
}
__device__ __forceinline__ void ldsm4(uint32_t* r, uint32_t addr) {
    asm volatile("ldmatrix.sync.aligned.m8n8.x4.shared.b16 {%0,%1,%2,%3}, [%4];"
                 : "=r"(r[0]), "=r"(r[1]), "=r"(r[2]), "=r"(r[3]) : "r"(addr));
}
__device__ __forceinline__ uint32_t smem_u32(const void* p) {
    return (uint32_t)__cvta_generic_to_shared(p);
}
__device__ __forceinline__ void cp16(void* dst, const void* src) {
    uint32_t s = (uint32_t)__cvta_generic_to_shared(dst);
    asm volatile("cp.async.cg.shared.global [%0], [%1], 16;\n" :: "r"(s), "l"(src));
}
#define CP_COMMIT asm volatile("cp.async.commit_group;\n")
#define CP_WAIT1  asm volatile("cp.async.wait_group 1;\n")
#define CP_WAIT0  asm volatile("cp.async.wait_group 0;\n")

// ---------------------------------------------------------------------------
__global__ void rot_kernel() {
    int k = blockIdx.x, d = threadIdx.x;
    int i = d & 31;
    float w = expf(-(float)i * (logf(10000.0f) / 31.0f));
    float ang = (float)k * w;
    g_rot[k * 64 + d] = (d < 32) ? sinf(ang) : cosf(ang);
}

__global__ __launch_bounds__(256) void prep_x(const float* __restrict__ X) {
    int idx = blockIdx.x * 256 + threadIdx.x;
    float4 v = ((const float4*)X)[idx];
    uint2 hi, lo; split4(v, hi, lo);
    ((uint2*)g_xh)[idx] = hi;
    ((uint2*)g_xl)[idx] = lo;
}

__global__ __launch_bounds__(256) void prep_w(const float* __restrict__ W) {
    __shared__ float tile[32][33];
    int n0 = blockIdx.x * 32, k0 = blockIdx.y * 32;
    int t = threadIdx.x;
    int row = t >> 3, c4 = (t & 7) * 4;
    float4 v = *(const float4*)&W[(size_t)(k0 + row) * 2048 + n0 + c4];
    tile[row][c4 + 0] = v.x; tile[row][c4 + 1] = v.y;
    tile[row][c4 + 2] = v.z; tile[row][c4 + 3] = v.w;
    __syncthreads();
    float4 o = make_float4(tile[c4 + 0][row], tile[c4 + 1][row],
                           tile[c4 + 2][row], tile[c4 + 3][row]);
    uint2 hi, lo; split4(o, hi, lo);
    *(uint2*)&g_wth[(size_t)(n0 + row) * 1024 + k0 + c4] = hi;
    *(uint2*)&g_wtl[(size_t)(n0 + row) * 1024 + k0 + c4] = lo;
}

// ---------------------------------------------------------------------------
// qv GEMM: 128x64 CTA tile, 3-term fp16 split, f32 accum everywhere.
// 3-STAGE cp.async pipeline, prefetch distance 2, ONE sync per iteration.
// ---------------------------------------------------------------------------
#define QV_PA (128*40)
#define QV_PB (64*40)
#define QV_SS (2*QV_PA + 2*QV_PB)   // 15360 halves per stage
#define QV_SMEM (3*QV_SS*2)         // 92160 B

__device__ __forceinline__ void qv_issue(__half* qsm, int stage, int k0,
                                         int m0, int n0, int t) {
    __half* base = qsm + stage * QV_SS;
    #pragma unroll
    for (int i = 0; i < 2; i++) {
        int c = t + 256 * i;
        int row = c >> 2, seg = (c & 3) * 8;
        size_t ga = (size_t)(m0 + row) * 1024 + k0 + seg;
        cp16(base + row * 40 + seg,          g_xh + ga);
        cp16(base + QV_PA + row * 40 + seg,  g_xl + ga);
    }
    {
        int row = t >> 2, seg = (t & 3) * 8;
        size_t gb = (size_t)(n0 + row) * 1024 + k0 + seg;
        cp16(base + 2 * QV_PA + row * 40 + seg,          g_wth + gb);
        cp16(base + 2 * QV_PA + QV_PB + row * 40 + seg,  g_wtl + gb);
    }
}

__global__ __launch_bounds__(256, 2) void qv_gemm_f16() {
    extern __shared__ __half qsm[];
    int t = threadIdx.x, lane = t & 31, warp = t >> 5;
    int m0 = blockIdx.y * 128, n0 = blockIdx.x * 64;
    int wm = (warp >> 1) * 32, wn = (warp & 1) * 32;
    int r = lane >> 2, c2 = (lane & 3) * 2;

    int lane7 = lane & 7;
    int lrow = lane7 + ((lane >> 3) & 1) * 8;
    int acol = ((lane >> 4) & 1) * 8;
    uint32_t offA0 = ((wm + lrow) * 40 + acol) * 2;
    uint32_t offA1 = ((wm + 16 + lrow) * 40 + acol) * 2;
    int brow = ((lane >> 4) & 1) * 8 + lane7;
    int bcol = ((lane >> 3) & 1) * 8;
    uint32_t offB[2];
    #pragma unroll
    for (int j = 0; j < 2; j++) offB[j] = ((wn + j * 16 + brow) * 40 + bcol) * 2;
    uint32_t sQ = smem_u32(qsm);

    float acc[2][4][4];
    #pragma unroll
    for (int mt = 0; mt < 2; mt++)
        #pragma unroll
        for (int nt = 0; nt < 4; nt++)
            #pragma unroll
            for (int j = 0; j < 4; j++) acc[mt][nt][j] = 0.f;

    qv_issue(qsm, 0, 0, m0, n0, t);
    CP_COMMIT;
    qv_issue(qsm, 1, 32, m0, n0, t);
    CP_COMMIT;

    for (int it = 0; it < 32; it++) {
        if (it == 31) { CP_WAIT0; } else { CP_WAIT1; }
        __syncthreads();

        uint32_t stB = sQ + (it % 3) * (QV_SS * 2);
        uint32_t aH = stB;
        uint32_t aL = stB + QV_PA * 2;
        uint32_t bH = stB + 2 * QV_PA * 2;
        uint32_t bL = stB + (2 * QV_PA + QV_PB) * 2;

        #pragma unroll
        for (int s = 0; s < 2; s++) {
            uint32_t ah0[4], ah1[4], al0[4], al1[4];
            ldsm4(ah0, aH + offA0 + s * 32);
            ldsm4(ah1, aH + offA1 + s * 32);
            ldsm4(al0, aL + offA0 + s * 32);
            ldsm4(al1, aL + offA1 + s * 32);
            #pragma unroll
            for (int j = 0; j < 2; j++) {
                uint32_t b_h[4], b_l[4];
                ldsm4(b_h, bH + offB[j] + s * 32);
                ldsm4(b_l, bL + offB[j] + s * 32);
                mma_f16(acc[0][2 * j],     ah0, &b_h[0]);
                mma_f16(acc[1][2 * j],     ah1, &b_h[0]);
                mma_f16(acc[0][2 * j + 1], ah0, &b_h[2]);
                mma_f16(acc[1][2 * j + 1], ah1, &b_h[2]);
                mma_f16(acc[0][2 * j],     ah0, &b_l[0]);
                mma_f16(acc[1][2 * j],     ah1, &b_l[0]);
                mma_f16(acc[0][2 * j + 1], ah0, &b_l[2]);
                mma_f16(acc[1][2 * j + 1], ah1, &b_l[2]);
                mma_f16(acc[0][2 * j],     al0, &b_h[0]);
                mma_f16(acc[1][2 * j],     al1, &b_h[0]);
                mma_f16(acc[0][2 * j + 1], al0, &b_h[2]);
                mma_f16(acc[1][2 * j + 1], al1, &b_h[2]);
            }
        }

        if (it < 30) {
            qv_issue(qsm, (it + 2) % 3, (it + 2) * 32, m0, n0, t);
            CP_COMMIT;
        }
    }

    #pragma unroll
    for (int mt = 0; mt < 2; mt++) {
        #pragma unroll
        for (int nt = 0; nt < 4; nt++) {
            int r0 = m0 + wm + mt * 16 + r;
            int cc = n0 + wn + nt * 8 + c2;
            #pragma unroll
            for (int half_ = 0; half_ < 2; half_++) {
                int m = r0 + half_ * 8;
                float2 val = make_float2(acc[mt][nt][half_ * 2],
                                         acc[mt][nt][half_ * 2 + 1]);
                int bi = m >> 9, l = m & 511;
                if (cc < 1024) {
                    int h = cc >> 6, d = cc & 63;
                    *(float2*)&g_q[(((size_t)(bi * 16 + h) * 512) + l) * 64 + d] = val;
                } else {
                    int n2 = cc - 1024;
                    int h = n2 >> 6, d = n2 & 63;
                    *(float2*)&g_v[(((size_t)(bi * 16 + h) * 512) + l) * 64 + d] = val;
                }
            }
        }
    }
}

// ---------------------------------------------------------------------------
__global__ __launch_bounds__(256) void qe_build(const float* __restrict__ rr,
                                                const float* __restrict__ rw) {
    __shared__ float u[4][64];
    int bh = blockIdx.x, h = bh & 15;
    int row = threadIdx.x >> 6;
    int d = threadIdx.x & 63;
    int q = blockIdx.y * 4 + row;

    float qv = g_q[((size_t)bh * 512 + q) * 64 + d];
    float outA = qv + rr[h * 64 + d];
    float uu = qv + rw[h * 64 + d];
    u[row][d] = uu;
    __syncthreads();
    int i = d & 31;
    float sq = g_rot[q * 64 + i];
    float cq = g_rot[q * 64 + 32 + i];
    float partner = u[row][d ^ 32];
    float outB = uu * cq + ((d < 32) ? partner : -partner) * sq;

    size_t base = ((size_t)bh * 512 + q) * 128;
    __half ha = __float2half_rn(outA);
    __half hb = __float2half_rn(outB);
    g_qeh[base + d] = ha;
    g_qeh[base + 64 + d] = hb;
    g_qel[base + d] = __float2half_rn(outA - __half2float(ha));
    g_qel[base + 64 + d] = __float2half_rn(outB - __half2float(hb));
}

__global__ __launch_bounds__(256) void ke_build(const float* __restrict__ X) {
    int bh = blockIdx.x;
    int b = bh >> 4, h = bh & 15;
    int kbase = blockIdx.y * 64;
    for (int i = threadIdx.x; i < 64 * 128; i += 256) {
        int k = kbase + (i >> 7), c = i & 127;
        float f = (c < 64) ? X[((size_t)(b * 512) + k) * 1024 + h * 64 + c]
                           : g_rot[k * 64 + (c - 64)];
        __half hi = __float2half_rn(f);
        size_t o = ((size_t)bh * 512 + k) * 128 + c;
        g_keh[o] = hi;
        g_kel[o] = __float2half_rn(f - __half2float(hi));
    }
}

__global__ __launch_bounds__(256) void build_vt() {
    __shared__ float tile[64][65];
    int bh = blockIdx.x;
    int k0 = blockIdx.y * 64;
    int t = threadIdx.x;
    #pragma unroll
    for (int i = 0; i < 4; i++) {
        int idx = t + 256 * i;
        int kk = idx >> 4, d4 = (idx & 15) * 4;
        float4 v = *(const float4*)&g_v[((size_t)bh * 512 + k0 + kk) * 64 + d4];
        tile[kk][d4 + 0] = v.x; tile[kk][d4 + 1] = v.y;
        tile[kk][d4 + 2] = v.z; tile[kk][d4 + 3] = v.w;
    }
    __syncthreads();
    #pragma unroll
    for (int i = 0; i < 4; i++) {
        int idx = t + 256 * i;
        int d = idx >> 4, kk4 = (idx & 15) * 4;
        float4 o = make_float4(tile[kk4 + 0][d], tile[kk4 + 1][d],
                               tile[kk4 + 2][d], tile[kk4 + 3][d]);
        uint2 hi, lo; split4(o, hi, lo);
        *(uint2*)&g_vth[((size_t)bh * 64 + d) * 512 + k0 + kk4] = hi;
        *(uint2*)&g_vtl[((size_t)bh * 64 + d) * 512 + k0 + kk4] = lo;
    }
}

// ---------------------------------------------------------------------------
// Flash attention (R13, unchanged): q-tile 128, 256 threads, 2-stage cp.async,
// ldmatrix frags, Q hoisted, 3-term S and 3-term PV, all f32 accum.
// ---------------------------------------------------------------------------
#define QK_STR 136
#define V_STR  72
#define F_QSZ (128*QK_STR)
#define F_KSZ (64*QK_STR)
#define F_VSZ (64*V_STR)
#define F_KBASE (2*F_QSZ)
#define F_VBASE (2*F_QSZ + 4*F_KSZ)
#define F_END   (2*F_QSZ + 4*F_KSZ + 4*F_VSZ)
#define FLASH_SMEM (F_END*2 + 512*4)

__device__ __forceinline__ void flash_issue_kv(__half* sh, int stage, int k0,
                                               int bh, int t) {
    __half* Kh = sh + F_KBASE + stage * 2 * F_KSZ;
    __half* Kl = Kh + F_KSZ;
    __half* Vh = sh + F_VBASE + stage * 2 * F_VSZ;
    __half* Vl = Vh + F_VSZ;
    #pragma unroll
    for (int i = 0; i < 4; i++) {
        int c = t + 256 * i;
        int k = c >> 4, seg = (c & 15) * 8;
        size_t g = ((size_t)bh * 512 + k0 + k) * 128 + seg;
        cp16(Kh + k * QK_STR + seg, g_keh + g);
        cp16(Kl + k * QK_STR + seg, g_kel + g);
    }
    #pragma unroll
    for (int i = 0; i < 2; i++) {
        int c = t + 256 * i;
        int d = c >> 3, seg = (c & 7) * 8;
        size_t g = ((size_t)bh * 64 + d) * 512 + k0 + seg;
        cp16(Vh + d * V_STR + seg, g_vth + g);
        cp16(Vl + d * V_STR + seg, g_vtl + g);
    }
}

__global__ __launch_bounds__(256) void flash_attn(const float* __restrict__ mask,
                                                  float* __restrict__ out) {
    extern __shared__ __half sh[];
    float* ms = (float*)(sh + F_END);

    int qt = blockIdx.x, bh = blockIdx.y;
    int b = bh >> 4, h = bh & 15;
    int q0 = qt * 128;
    int t = threadIdx.x, lane = t & 31, warp = t >> 5;
    int r = lane >> 2, c2 = (lane & 3) * 2;
    int wq = warp * 16;

    int lane7 = lane & 7;
    int lrow = lane7 + ((lane >> 3) & 1) * 8;
    int acol = ((lane >> 4) & 1) * 8;
    uint32_t offQ = ((wq + lrow) * QK_STR + acol) * 2;
    int brow = ((lane >> 4) & 1) * 8 + lane7;
    int bcol = ((lane >> 3) & 1) * 8;
    uint32_t offK[4], offV[4];
    #pragma unroll
    for (int j = 0; j < 4; j++) {
        offK[j] = ((j * 16 + brow) * QK_STR + bcol) * 2;
        offV[j] = ((j * 16 + brow) * V_STR + bcol) * 2;
    }
    uint32_t sF = smem_u32(sh);

    #pragma unroll
    for (int i = 0; i < 8; i++) {
        int c = t + 256 * i;
        int q = c >> 4, seg = (c & 15) * 8;
        size_t g = ((size_t)bh * 512 + q0 + q) * 128 + seg;
        cp16(sh + q * QK_STR + seg, g_qeh + g);
        cp16(sh + F_QSZ + q * QK_STR + seg, g_qel + g);
    }
    flash_issue_kv(sh, 0, 0, bh, t);
    CP_COMMIT;

    ms[t] = mask[b * 512 + t];
    ms[t + 256] = mask[b * 512 + t + 256];

    float m_run[2] = {-1e30f, -1e30f}, l_run[2] = {0.f, 0.f};
    float o[8][4];
    #pragma unroll
    for (int nt = 0; nt < 8; nt++)
        #pragma unroll
        for (int j = 0; j < 4; j++) o[nt][j] = 0.f;

    uint32_t qh[8][4], ql[8][4];

    for (int it = 0; it < 8; it++) {
        if (it < 7) {
            flash_issue_kv(sh, (it + 1) & 1, (it + 1) * 64, bh, t);
            CP_COMMIT;
            CP_WAIT1;
        } else {
            CP_WAIT0;
        }
        __syncthreads();

        if (it == 0) {
            #pragma unroll
            for (int st = 0; st < 8; st++) {
                ldsm4(qh[st], sF + offQ + st * 32);
                ldsm4(ql[st], sF + F_QSZ * 2 + offQ + st * 32);
            }
        }

        uint32_t aKh = sF + (F_KBASE + (it & 1) * 2 * F_KSZ) * 2;
        uint32_t aKl = aKh + F_KSZ * 2;
        uint32_t aVh = sF + (F_VBASE + (it & 1) * 2 * F_VSZ) * 2;
        uint32_t aVl = aVh + F_VSZ * 2;
        int k0 = it * 64;

        float s[8][4];
        #pragma unroll
        for (int nt = 0; nt < 8; nt++)
            #pragma unroll
            for (int j = 0; j < 4; j++) s[nt][j] = 0.f;

        #pragma unroll
        for (int st = 0; st < 8; st++) {
            #pragma unroll
            for (int j = 0; j < 4; j++) {
                uint32_t kh4[4], kl4[4];
                ldsm4(kh4, aKh + offK[j] + st * 32);
                ldsm4(kl4, aKl + offK[j] + st * 32);
                mma_f16(s[2 * j],     qh[st], &kh4[0]);
                mma_f16(s[2 * j],     qh[st], &kl4[0]);
                mma_f16(s[2 * j],     ql[st], &kh4[0]);
                mma_f16(s[2 * j + 1], qh[st], &kh4[2]);
                mma_f16(s[2 * j + 1], qh[st], &kl4[2]);
                mma_f16(s[2 * j + 1], ql[st], &kh4[2]);
            }
        }

        float mnew0 = m_run[0], mnew1 = m_run[1];
        #pragma unroll
        for (int nt = 0; nt < 8; nt++) {
            int kc = k0 + nt * 8 + c2;
            float mk0 = ms[kc], mk1 = ms[kc + 1];
            float v0 = s[nt][0] * mk0; s[nt][0] = (v0 == 0.f) ? -INFINITY : v0;
            float v1 = s[nt][1] * mk1; s[nt][1] = (v1 == 0.f) ? -INFINITY : v1;
            float v2 = s[nt][2] * mk0; s[nt][2] = (v2 == 0.f) ? -INFINITY : v2;
            float v3 = s[nt][3] * mk1; s[nt][3] = (v3 == 0.f) ? -INFINITY : v3;
            mnew0 = fmaxf(mnew0, fmaxf(s[nt][0], s[nt][1]));
            mnew1 = fmaxf(mnew1, fmaxf(s[nt][2], s[nt][3]));
        }
        #pragma unroll
        for (int off = 1; off <= 2; off <<= 1) {
            mnew0 = fmaxf(mnew0, __shfl_xor_sync(0xffffffffu, mnew0, off));
            mnew1 = fmaxf(mnew1, __shfl_xor_sync(0xffffffffu, mnew1, off));
        }
        float corr0 = __expf(m_run[0] - mnew0);
        float corr1 = __expf(m_run[1] - mnew1);
        float ts0 = 0.f, ts1 = 0.f;
        #pragma unroll
        for (int nt = 0; nt < 8; nt++) {
            float p0 = __expf(s[nt][0] - mnew0); s[nt][0] = p0;
            float p1 = __expf(s[nt][1] - mnew0); s[nt][1] = p1;
            float p2 = __expf(s[nt][2] - mnew1); s[nt][2] = p2;
            float p3 = __expf(s[nt][3] - mnew1); s[nt][3] = p3;
            ts0 += p0 + p1; ts1 += p2 + p3;
        }
        #pragma unroll
        for (int off = 1; off <= 2; off <<= 1) {
            ts0 += __shfl_xor_sync(0xffffffffu, ts0, off);
            ts1 += __shfl_xor_sync(0xffffffffu, ts1, off);
        }
        l_run[0] = l_run[0] * corr0 + ts0;
        l_run[1] = l_run[1] * corr1 + ts1;
        m_run[0] = mnew0; m_run[1] = mnew1;
        #pragma unroll
        for (int nt = 0; nt < 8; nt++) {
            o[nt][0] *= corr0; o[nt][1] *= corr0;
            o[nt][2] *= corr1; o[nt][3] *= corr1;
        }

        #pragma unroll
        for (int s2 = 0; s2 < 4; s2++) {
            float* pa = s[2 * s2];
            float* pb = s[2 * s2 + 1];
            __half h00 = __float2half_rn(pa[0]), h01 = __float2half_rn(pa[1]);
            __half h02 = __float2half_rn(pa[2]), h03 = __float2half_rn(pa[3]);
            __half h10 = __float2half_rn(pb[0]), h11 = __float2half_rn(pb[1]);
            __half h12 = __float2half_rn(pb[2]), h13 = __float2half_rn(pb[3]);
            uint32_t ph[4], pl[4];
            ph[0] = pack2h(h00, h01);
            ph[1] = pack2h(h02, h03);
            ph[2] = pack2h(h10, h11);
            ph[3] = pack2h(h12, h13);
            pl[0] = pack2h(__float2half_rn(pa[0] - __half2float(h00)),
                           __float2half_rn(pa[1] - __half2float(h01)));
            pl[1] = pack2h(__float2half_rn(pa[2] - __half2float(h02)),
                           __float2half_rn(pa[3] - __half2float(h03)));
            pl[2] = pack2h(__float2half_rn(pb[0] - __half2float(h10)),
                           __float2half_rn(pb[1] - __half2float(h11)));
            pl[3] = pack2h(__float2half_rn(pb[2] - __half2float(h12)),
                           __float2half_rn(pb[3] - __half2float(h13)));
            #pragma unroll
            for (int j = 0; j < 4; j++) {
                uint32_t vh4[4], vl4[4];
                ldsm4(vh4, aVh + offV[j] + s2 * 32);
                ldsm4(vl4, aVl + offV[j] + s2 * 32);
                mma_f16(o[2 * j],     ph, &vh4[0]);
                mma_f16(o[2 * j + 1], ph, &vh4[2]);
                mma_f16(o[2 * j],     ph, &vl4[0]);
                mma_f16(o[2 * j + 1], ph, &vl4[2]);
                mma_f16(o[2 * j],     pl, &vh4[0]);
                mma_f16(o[2 * j + 1], pl, &vh4[2]);
            }
        }
        __syncthreads();
    }

    float inv0 = 1.0f / l_run[0], inv1 = 1.0f / l_run[1];
    int qg0 = q0 + wq + r;
    #pragma unroll
    for (int ntd = 0; ntd < 8; ntd++) {
        int d = ntd * 8 + c2;
        *(float2*)&out[((size_t)(b * 512) + qg0) * 1024 + h * 64 + d] =
            make_float2(o[ntd][0] * inv0, o[ntd][1] * inv0);
        *(float2*)&out[((size_t)(b * 512) + qg0 + 8) * 1024 + h * 64 + d] =
            make_float2(o[ntd][2] * inv1, o[ntd][3] * inv1);
    }
}

// ---------------------------------------------------------------------------
extern "C" void kernel_launch(void* const* d_in, const int* in_sizes, int n_in,
                              void* d_out, int out_size) {
    const float* x    = (const float*)d_in[0];
    const float* mask = (const float*)d_in[1];
    const float* W    = (const float*)d_in[2];
    const float* rr   = (const float*)d_in[3];
    const float* rw   = (const float*)d_in[4];
    float* out = (float*)d_out;

    cudaFuncSetAttribute(qv_gemm_f16, cudaFuncAttributeMaxDynamicSharedMemorySize,
                         QV_SMEM);
    cudaFuncSetAttribute(flash_attn, cudaFuncAttributeMaxDynamicSharedMemorySize,
                         FLASH_SMEM);

    rot_kernel<<<512, 64>>>();
    prep_x<<<4096, 256>>>(x);
    prep_w<<<dim3(64, 32), 256>>>(W);
    qv_gemm_f16<<<dim3(32, 32), 256, QV_SMEM>>>();
    qe_build<<<dim3(128, 128), 256>>>(rr, rw);
    ke_build<<<dim3(128, 8), 256>>>(x);
    build_vt<<<dim3(128, 8), 256>>>();
    flash_attn<<<dim3(4, 128), 256, FLASH_SMEM>>>(mask, out);
}